// round 7
// baseline (speedup 1.0000x reference)
#include <cuda_runtime.h>
#include <cstdint>

#define NUM_GRAPHS 16384
#define EMB_DIM 128

// Precomputed segment boundaries (lower_bound of each graph id).
__device__ int g_offs_atoms[NUM_GRAPHS + 1];
__device__ int g_offs_frags[NUM_GRAPHS + 1];

__device__ __forceinline__ int idx_at(const void* __restrict__ b, int i, bool is64) {
    if (is64) return (int)(((const long long* __restrict__)b)[i]);
    return ((const int* __restrict__)b)[i];
}

// Ids sorted in [0,16384). As int32, position n-1 (odd) is an int64 high word
// => 0 under int64 layout; nonzero (largest id) under int32 layout.
__device__ __forceinline__ bool detect_is64(const void* __restrict__ b, int n) {
    return ((const int* __restrict__)b)[n - 1] == 0;
}

// Fused vectorized prologue: one launch covers both index arrays.
__global__ void build_offsets_fused(const void* __restrict__ a, int na, int* __restrict__ offsA,
                                    const void* __restrict__ f, int nf, int* __restrict__ offsF) {
    const int chunksA = (na + 7) >> 3;
    const int chunksF = (nf + 7) >> 3;
    const int total   = chunksA + chunksF;
    const int stride  = gridDim.x * blockDim.x;

    for (int c = blockIdx.x * blockDim.x + threadIdx.x; c < total; c += stride) {
        const bool isF = (c >= chunksA);
        const void* __restrict__ b = isF ? f : a;
        const int n = isF ? nf : na;
        int* __restrict__ offs = isF ? offsF : offsA;
        const int base = (isF ? (c - chunksA) : c) << 3;
        const bool is64 = detect_is64(b, n);

        int ids[8];
        if (base + 8 <= n) {
            if (is64) {
                const ulonglong2* p = (const ulonglong2*)((const long long*)b + base);
                ulonglong2 v0 = __ldcg(p), v1 = __ldcg(p + 1), v2 = __ldcg(p + 2), v3 = __ldcg(p + 3);
                ids[0] = (int)v0.x; ids[1] = (int)v0.y;
                ids[2] = (int)v1.x; ids[3] = (int)v1.y;
                ids[4] = (int)v2.x; ids[5] = (int)v2.y;
                ids[6] = (int)v3.x; ids[7] = (int)v3.y;
            } else {
                const int4* p = (const int4*)((const int*)b + base);
                int4 v0 = __ldcg(p), v1 = __ldcg(p + 1);
                ids[0] = v0.x; ids[1] = v0.y; ids[2] = v0.z; ids[3] = v0.w;
                ids[4] = v1.x; ids[5] = v1.y; ids[6] = v1.z; ids[7] = v1.w;
            }
            int prev = (base == 0) ? -1 : idx_at(b, base - 1, is64);
            #pragma unroll
            for (int j = 0; j < 8; j++) {
                const int cur = ids[j];
                if (cur != prev) {
                    for (int id = prev + 1; id <= cur; ++id) offs[id] = base + j;
                    prev = cur;
                }
            }
            if (base + 8 == n) {
                for (int id = ids[7] + 1; id <= NUM_GRAPHS; ++id) offs[id] = n;
            }
        } else {
            int prev = (base == 0) ? -1 : idx_at(b, base - 1, is64);
            for (int i = base; i < n; i++) {
                const int cur = idx_at(b, i, is64);
                for (int id = prev + 1; id <= cur; ++id) offs[id] = i;
                prev = cur;
                if (i == n - 1) {
                    for (int id = cur + 1; id <= NUM_GRAPHS; ++id) offs[id] = n;
                }
            }
        }
    }
}

__device__ __forceinline__ void acc_add2(float2& a, const float2& v) {
    a.x += v.x; a.y += v.y;
}

// Dim-split pooling: CTA (g, h) sums dim-half h (64 floats) of graph g's atom
// and frag rows. Halves write disjoint output columns => no combine needed,
// every 32B sector of the input is still read exactly once.
__global__ __launch_bounds__(128, 12)
void fragnet_pool_kernel(const float* __restrict__ x_atoms,
                         const float* __restrict__ x_frags,
                         float* __restrict__ out) {
    const int g    = blockIdx.x;
    const int h    = blockIdx.y;            // dim half: 0 or 1
    const int warp = threadIdx.x >> 5;
    const int lane = threadIdx.x & 31;
    const int dofs = h * 64 + lane * 2;     // float2 per lane => 64 dims per warp

    __shared__ int bounds[4];               // [a_start, a_end, f_start, f_end]
    __shared__ float2 shA[4][32];
    __shared__ float2 shF[4][32];

    if (threadIdx.x < 4) {
        const int* offs = (threadIdx.x >= 2) ? g_offs_frags : g_offs_atoms;
        bounds[threadIdx.x] = offs[g + (threadIdx.x & 1)];
    }
    __syncthreads();

    const int a_start = bounds[0], a_end = bounds[1];
    const int f_start = bounds[2], f_end = bounds[3];

    float2 accA0 = make_float2(0.f, 0.f);
    float2 accA1 = make_float2(0.f, 0.f);
    float2 accF0 = make_float2(0.f, 0.f);
    float2 accF1 = make_float2(0.f, 0.f);

    // Atoms: each warp strides rows by 4; per row-iter a warp reads 256B
    // contiguous (coalesced). Unroll 4 for MLP. L1-bypass (zero reuse).
    {
        const float* __restrict__ base = x_atoms + dofs;
        int r = a_start + warp;
        for (; r + 12 < a_end; r += 16) {
            float2 v0 = __ldcg(reinterpret_cast<const float2*>(base + (size_t)r * EMB_DIM));
            float2 v1 = __ldcg(reinterpret_cast<const float2*>(base + (size_t)(r + 4) * EMB_DIM));
            float2 v2 = __ldcg(reinterpret_cast<const float2*>(base + (size_t)(r + 8) * EMB_DIM));
            float2 v3 = __ldcg(reinterpret_cast<const float2*>(base + (size_t)(r + 12) * EMB_DIM));
            acc_add2(accA0, v0); acc_add2(accA1, v1);
            acc_add2(accA0, v2); acc_add2(accA1, v3);
        }
        for (; r < a_end; r += 4) {
            float2 v = __ldcg(reinterpret_cast<const float2*>(base + (size_t)r * EMB_DIM));
            acc_add2(accA0, v);
        }
    }
    // Frags
    {
        const float* __restrict__ base = x_frags + dofs;
        int r = f_start + warp;
        for (; r + 12 < f_end; r += 16) {
            float2 v0 = __ldcg(reinterpret_cast<const float2*>(base + (size_t)r * EMB_DIM));
            float2 v1 = __ldcg(reinterpret_cast<const float2*>(base + (size_t)(r + 4) * EMB_DIM));
            float2 v2 = __ldcg(reinterpret_cast<const float2*>(base + (size_t)(r + 8) * EMB_DIM));
            float2 v3 = __ldcg(reinterpret_cast<const float2*>(base + (size_t)(r + 12) * EMB_DIM));
            acc_add2(accF0, v0); acc_add2(accF1, v1);
            acc_add2(accF0, v2); acc_add2(accF1, v3);
        }
        for (; r < f_end; r += 4) {
            float2 v = __ldcg(reinterpret_cast<const float2*>(base + (size_t)r * EMB_DIM));
            acc_add2(accF0, v);
        }
    }

    acc_add2(accA0, accA1);
    acc_add2(accF0, accF1);
    shA[warp][lane] = accA0;
    shF[warp][lane] = accF0;
    __syncthreads();

    // Warp 0 reduces+writes the atoms half-columns, warp 1 the frags.
    if (warp < 2) {
        const float2 (*sh)[32] = (warp == 0) ? shA : shF;
        float2 a0 = sh[0][lane], a1 = sh[1][lane], a2 = sh[2][lane], a3 = sh[3][lane];
        float2 s = make_float2(a0.x + a1.x + a2.x + a3.x,
                               a0.y + a1.y + a2.y + a3.y);
        // atoms -> cols [h*64, h*64+64); frags -> cols [128 + h*64, ...)
        float* dst = out + (size_t)g * (2 * EMB_DIM) + warp * EMB_DIM + h * 64;
        reinterpret_cast<float2*>(dst)[lane] = s;
    }
}

extern "C" void kernel_launch(void* const* d_in, const int* in_sizes, int n_in,
                              void* d_out, int out_size) {
    const float* x_atoms    = (const float*)d_in[0];
    const float* x_frags    = (const float*)d_in[1];
    const void*  batch      = d_in[2];
    const void*  frag_batch = d_in[3];
    float* out = (float*)d_out;

    const int n_atoms = in_sizes[2];
    const int n_frags = in_sizes[3];

    int* offs_atoms = nullptr;
    int* offs_frags = nullptr;
    cudaGetSymbolAddress((void**)&offs_atoms, g_offs_atoms);
    cudaGetSymbolAddress((void**)&offs_frags, g_offs_frags);

    const int chunks = ((n_atoms + 7) >> 3) + ((n_frags + 7) >> 3);
    const int T = 256;
    build_offsets_fused<<<(chunks + T - 1) / T, T>>>(batch, n_atoms, offs_atoms,
                                                     frag_batch, n_frags, offs_frags);
    dim3 grid(NUM_GRAPHS, 2);
    fragnet_pool_kernel<<<grid, 128>>>(x_atoms, x_frags, out);
}

// round 8
// speedup vs baseline: 1.0752x; 1.0752x over previous
#include <cuda_runtime.h>
#include <cstdint>

#define NUM_GRAPHS 16384
#define EMB_DIM 128

// Precomputed segment boundaries (lower_bound of each graph id).
__device__ int g_offs_atoms[NUM_GRAPHS + 1];
__device__ int g_offs_frags[NUM_GRAPHS + 1];
// Work-stealing counter for the pool kernel; reset by the prologue each launch.
__device__ int g_work_counter;

__device__ __forceinline__ int idx_at(const void* __restrict__ b, int i, bool is64) {
    if (is64) return (int)(((const long long* __restrict__)b)[i]);
    return ((const int* __restrict__)b)[i];
}

// Ids sorted in [0,16384). As int32, position n-1 (odd) is an int64 high word
// => 0 under int64 layout; nonzero (largest id) under int32 layout.
__device__ __forceinline__ bool detect_is64(const void* __restrict__ b, int n) {
    return ((const int* __restrict__)b)[n - 1] == 0;
}

// Fused vectorized prologue: one launch covers both index arrays. Also resets
// the work counter (stream-ordered before the pool kernel => capture-safe).
__global__ void build_offsets_fused(const void* __restrict__ a, int na, int* __restrict__ offsA,
                                    const void* __restrict__ f, int nf, int* __restrict__ offsF) {
    if (blockIdx.x == 0 && threadIdx.x == 0) g_work_counter = 0;

    const int chunksA = (na + 7) >> 3;
    const int chunksF = (nf + 7) >> 3;
    const int total   = chunksA + chunksF;
    const int stride  = gridDim.x * blockDim.x;

    for (int c = blockIdx.x * blockDim.x + threadIdx.x; c < total; c += stride) {
        const bool isF = (c >= chunksA);
        const void* __restrict__ b = isF ? f : a;
        const int n = isF ? nf : na;
        int* __restrict__ offs = isF ? offsF : offsA;
        const int base = (isF ? (c - chunksA) : c) << 3;
        const bool is64 = detect_is64(b, n);

        int ids[8];
        if (base + 8 <= n) {
            if (is64) {
                const ulonglong2* p = (const ulonglong2*)((const long long*)b + base);
                ulonglong2 v0 = __ldcg(p), v1 = __ldcg(p + 1), v2 = __ldcg(p + 2), v3 = __ldcg(p + 3);
                ids[0] = (int)v0.x; ids[1] = (int)v0.y;
                ids[2] = (int)v1.x; ids[3] = (int)v1.y;
                ids[4] = (int)v2.x; ids[5] = (int)v2.y;
                ids[6] = (int)v3.x; ids[7] = (int)v3.y;
            } else {
                const int4* p = (const int4*)((const int*)b + base);
                int4 v0 = __ldcg(p), v1 = __ldcg(p + 1);
                ids[0] = v0.x; ids[1] = v0.y; ids[2] = v0.z; ids[3] = v0.w;
                ids[4] = v1.x; ids[5] = v1.y; ids[6] = v1.z; ids[7] = v1.w;
            }
            int prev = (base == 0) ? -1 : idx_at(b, base - 1, is64);
            #pragma unroll
            for (int j = 0; j < 8; j++) {
                const int cur = ids[j];
                if (cur != prev) {
                    for (int id = prev + 1; id <= cur; ++id) offs[id] = base + j;
                    prev = cur;
                }
            }
            if (base + 8 == n) {
                for (int id = ids[7] + 1; id <= NUM_GRAPHS; ++id) offs[id] = n;
            }
        } else {
            int prev = (base == 0) ? -1 : idx_at(b, base - 1, is64);
            for (int i = base; i < n; i++) {
                const int cur = idx_at(b, i, is64);
                for (int id = prev + 1; id <= cur; ++id) offs[id] = i;
                prev = cur;
                if (i == n - 1) {
                    for (int id = cur + 1; id <= NUM_GRAPHS; ++id) offs[id] = n;
                }
            }
        }
    }
}

__device__ __forceinline__ void acc_add(float4& a, const float4& v) {
    a.x += v.x; a.y += v.y; a.z += v.z; a.w += v.w;
}

// Persistent warp-per-graph pooling with atomic work stealing.
// Each warp owns one graph at a time: 32 lanes x float4 = full 512B row per
// iteration (LDG.128, L1-bypass), unroll 4 rows for MLP. No shared memory,
// no __syncthreads — the warp reduces nothing across warps and writes both
// output halves itself.
__global__ __launch_bounds__(128, 8)
void fragnet_pool_kernel(const float* __restrict__ x_atoms,
                         const float* __restrict__ x_frags,
                         float* __restrict__ out) {
    const int lane = threadIdx.x & 31;

    while (true) {
        int g = 0;
        if (lane == 0) g = atomicAdd(&g_work_counter, 1);
        g = __shfl_sync(0xffffffffu, g, 0);
        if (g >= NUM_GRAPHS) break;

        // Bounds: lanes 0..3 load, then broadcast.
        int b = 0;
        if (lane < 2)      b = g_offs_atoms[g + lane];
        else if (lane < 4) b = g_offs_frags[g + lane - 2];
        const int a_start = __shfl_sync(0xffffffffu, b, 0);
        const int a_end   = __shfl_sync(0xffffffffu, b, 1);
        const int f_start = __shfl_sync(0xffffffffu, b, 2);
        const int f_end   = __shfl_sync(0xffffffffu, b, 3);

        float4 accA0 = make_float4(0.f, 0.f, 0.f, 0.f);
        float4 accA1 = make_float4(0.f, 0.f, 0.f, 0.f);

        // Atoms: rows stride 1 per warp; 4 rows (2KB contiguous) per trip.
        {
            int r = a_start;
            for (; r + 3 < a_end; r += 4) {
                float4 v0 = __ldcg(reinterpret_cast<const float4*>(x_atoms + (size_t)r * EMB_DIM) + lane);
                float4 v1 = __ldcg(reinterpret_cast<const float4*>(x_atoms + (size_t)(r + 1) * EMB_DIM) + lane);
                float4 v2 = __ldcg(reinterpret_cast<const float4*>(x_atoms + (size_t)(r + 2) * EMB_DIM) + lane);
                float4 v3 = __ldcg(reinterpret_cast<const float4*>(x_atoms + (size_t)(r + 3) * EMB_DIM) + lane);
                acc_add(accA0, v0); acc_add(accA1, v1);
                acc_add(accA0, v2); acc_add(accA1, v3);
            }
            for (; r < a_end; ++r) {
                float4 v = __ldcg(reinterpret_cast<const float4*>(x_atoms + (size_t)r * EMB_DIM) + lane);
                acc_add(accA0, v);
            }
            acc_add(accA0, accA1);
        }

        float4 accF0 = make_float4(0.f, 0.f, 0.f, 0.f);
        float4 accF1 = make_float4(0.f, 0.f, 0.f, 0.f);
        // Frags
        {
            int r = f_start;
            for (; r + 3 < f_end; r += 4) {
                float4 v0 = __ldcg(reinterpret_cast<const float4*>(x_frags + (size_t)r * EMB_DIM) + lane);
                float4 v1 = __ldcg(reinterpret_cast<const float4*>(x_frags + (size_t)(r + 1) * EMB_DIM) + lane);
                float4 v2 = __ldcg(reinterpret_cast<const float4*>(x_frags + (size_t)(r + 2) * EMB_DIM) + lane);
                float4 v3 = __ldcg(reinterpret_cast<const float4*>(x_frags + (size_t)(r + 3) * EMB_DIM) + lane);
                acc_add(accF0, v0); acc_add(accF1, v1);
                acc_add(accF0, v2); acc_add(accF1, v3);
            }
            for (; r < f_end; ++r) {
                float4 v = __ldcg(reinterpret_cast<const float4*>(x_frags + (size_t)r * EMB_DIM) + lane);
                acc_add(accF0, v);
            }
            acc_add(accF0, accF1);
        }

        // Write both halves of out[g, :]: atoms -> cols [0,128), frags -> [128,256).
        float4* dst = reinterpret_cast<float4*>(out + (size_t)g * (2 * EMB_DIM));
        dst[lane]      = accA0;
        dst[32 + lane] = accF0;
    }
}

extern "C" void kernel_launch(void* const* d_in, const int* in_sizes, int n_in,
                              void* d_out, int out_size) {
    const float* x_atoms    = (const float*)d_in[0];
    const float* x_frags    = (const float*)d_in[1];
    const void*  batch      = d_in[2];
    const void*  frag_batch = d_in[3];
    float* out = (float*)d_out;

    const int n_atoms = in_sizes[2];
    const int n_frags = in_sizes[3];

    int* offs_atoms = nullptr;
    int* offs_frags = nullptr;
    cudaGetSymbolAddress((void**)&offs_atoms, g_offs_atoms);
    cudaGetSymbolAddress((void**)&offs_frags, g_offs_frags);

    const int chunks = ((n_atoms + 7) >> 3) + ((n_frags + 7) >> 3);
    const int T = 256;
    build_offsets_fused<<<(chunks + T - 1) / T, T>>>(batch, n_atoms, offs_atoms,
                                                     frag_batch, n_frags, offs_frags);
    // Persistent grid: ~8 CTAs/SM on 152 SMs.
    fragnet_pool_kernel<<<1216, 128>>>(x_atoms, x_frags, out);
}